// round 13
// baseline (speedup 1.0000x reference)
#include <cuda_runtime.h>
#include <cuda_bf16.h>

#define LSE_EPS 1e-5f
#define LSE_ITER 4
#define WBUF_WORDS 288   // padded: neighbor n at word n*8 + (n>>2)*4, max 284

// Folded parameters: W1f[16] (o*4+c), t1[4] @16, W2f[32] @20 (o*4+c), t2[8] @52
__device__   float g_params[60];
__constant__ float c_params[60];

__global__ void lse_fold_params(const float* __restrict__ W1, const float* __restrict__ g1,
                                const float* __restrict__ b1, const float* __restrict__ m1,
                                const float* __restrict__ v1,
                                const float* __restrict__ W2, const float* __restrict__ g2,
                                const float* __restrict__ b2, const float* __restrict__ m2,
                                const float* __restrict__ v2) {
    int i = threadIdx.x;
    if (i < 4) {
        float s = g1[i] * rsqrtf(v1[i] + LSE_EPS);
        #pragma unroll
        for (int c = 0; c < 4; c++) g_params[i * 4 + c] = W1[i * 4 + c] * s;
        g_params[16 + i] = b1[i] - m1[i] * s;
    }
    if (i < 8) {
        float s = g2[i] * rsqrtf(v2[i] + LSE_EPS);
        #pragma unroll
        for (int c = 0; c < 4; c++) g_params[20 + i * 4 + c] = W2[i * 4 + c] * s;
        g_params[52 + i] = b2[i] - m2[i] * s;
    }
}

// Padded staging offset: neighbor n's 8 floats start at word n*8 + (n>>2)*4.
// Conflict-free per 8-lane phase for both STS.128 and LDS.128.
__device__ __forceinline__ int lse_off(int n) {
    return n * 8 + ((n >> 2) << 2);
}

// Hardware approximate sqrt: single MUFU.SQRT (sqrt.approx.f32).
// NOTE: __fsqrt_rn/__frsqrt_rn are the correctly-rounded (SOFTWARE-sequence)
// versions — using them regressed R11/R12. This is the real fast path.
__device__ __forceinline__ float lse_sqrt_approx(float s) {
    float d;
    asm("sqrt.approx.f32 %0, %1;" : "=f"(d) : "f"(s));
    return d;
}

__device__ __forceinline__ void lse_compute(float nx, float ny, float nz,
                                            float cx, float cy, float cz,
                                            float* __restrict__ r) {
    float rx = nx - cx;
    float ry = ny - cy;
    float rz = nz - cz;
    float d  = lse_sqrt_approx(fmaf(rx, rx, fmaf(ry, ry, rz * rz)));

    float h[4];
    #pragma unroll
    for (int o = 0; o < 4; o++) {
        float acc = c_params[16 + o];
        acc = fmaf(rx, c_params[o * 4 + 0], acc);
        acc = fmaf(ry, c_params[o * 4 + 1], acc);
        acc = fmaf(rz, c_params[o * 4 + 2], acc);
        acc = fmaf(d,  c_params[o * 4 + 3], acc);
        h[o] = fmaxf(acc, 0.0f);
    }

    #pragma unroll
    for (int o = 0; o < 8; o++) {
        float acc = c_params[52 + o];
        acc = fmaf(h[0], c_params[20 + o * 4 + 0], acc);
        acc = fmaf(h[1], c_params[20 + o * 4 + 1], acc);
        acc = fmaf(h[2], c_params[20 + o * 4 + 2], acc);
        acc = fmaf(h[3], c_params[20 + o * 4 + 3], acc);
        r[o] = fmaxf(acc, 0.0f);
    }
}

// Thread-per-neighbor, 4 neighbors/thread strided by blockDim. Loads batched
// up front for MLP. Stores staged through a single warp-private smem buffer;
// global writes are lane-dense float4 (proven R10 structure).
__global__ __launch_bounds__(256, 6) void lse_main(const float* __restrict__ coords,
                                                   const float* __restrict__ nbr,
                                                   float* __restrict__ out,
                                                   int total_nb) {
    __shared__ float sbuf[8 * WBUF_WORDS];

    int lane = threadIdx.x & 31;
    int warp = threadIdx.x >> 5;
    float* wbuf = sbuf + warp * WBUF_WORDS;

    int base = blockIdx.x * (256 * LSE_ITER) + threadIdx.x;

    if (base + 256 * (LSE_ITER - 1) < total_nb) {
        float nx[LSE_ITER], ny[LSE_ITER], nz[LSE_ITER];
        float cx[LSE_ITER], cy[LSE_ITER], cz[LSE_ITER];
        #pragma unroll
        for (int it = 0; it < LSE_ITER; it++) {
            int g = base + it * 256;
            const float* p = nbr + (size_t)g * 3;
            nx[it] = __ldg(p + 0);
            ny[it] = __ldg(p + 1);
            nz[it] = __ldg(p + 2);
            int bn = g >> 4;
            const float* q = coords + (size_t)bn * 3;
            cx[it] = __ldg(q + 0);
            cy[it] = __ldg(q + 1);
            cz[it] = __ldg(q + 2);
        }

        #pragma unroll
        for (int it = 0; it < LSE_ITER; it++) {
            float r[8];
            lse_compute(nx[it], ny[it], nz[it], cx[it], cy[it], cz[it], r);

            // Stage 32B result into padded smem (conflict-free STS.128 x2)
            float4* s = reinterpret_cast<float4*>(wbuf + lse_off(lane));
            s[0] = make_float4(r[0], r[1], r[2], r[3]);
            s[1] = make_float4(r[4], r[5], r[6], r[7]);
            __syncwarp();

            // Dense readback: float4 slot f -> neighbor f>>1, half f&1
            int f0 = lane, f1 = lane + 32;
            float4 v0 = *reinterpret_cast<const float4*>(
                wbuf + lse_off(f0 >> 1) + (f0 & 1) * 4);
            float4 v1 = *reinterpret_cast<const float4*>(
                wbuf + lse_off(f1 >> 1) + (f1 & 1) * 4);
            __syncwarp();

            // Lane-dense global store: warp writes 1KB fully contiguous
            int g0 = (base - lane) + it * 256;           // warp's first neighbor
            float4* ob = reinterpret_cast<float4*>(out + (size_t)g0 * 8);
            ob[lane]      = v0;
            ob[lane + 32] = v1;
        }
    } else {
        // Tail path (not taken for the benchmark shape): direct stores.
        for (int it = 0; it < LSE_ITER; it++) {
            int g = base + it * 256;
            if (g < total_nb) {
                const float* p = nbr + (size_t)g * 3;
                int bn = g >> 4;
                const float* q = coords + (size_t)bn * 3;
                float r[8];
                lse_compute(__ldg(p), __ldg(p + 1), __ldg(p + 2),
                            __ldg(q), __ldg(q + 1), __ldg(q + 2), r);
                float4* ob = reinterpret_cast<float4*>(out + (size_t)g * 8);
                ob[0] = make_float4(r[0], r[1], r[2], r[3]);
                ob[1] = make_float4(r[4], r[5], r[6], r[7]);
            }
        }
    }
}

extern "C" void kernel_launch(void* const* d_in, const int* in_sizes, int n_in,
                              void* d_out, int out_size) {
    const float* coords = (const float*)d_in[0];   // (B,N,3)
    const float* nbr    = (const float*)d_in[1];   // (B,N,K,3)
    const float* W1 = (const float*)d_in[2];
    const float* g1 = (const float*)d_in[3];
    const float* b1 = (const float*)d_in[4];
    const float* m1 = (const float*)d_in[5];
    const float* v1 = (const float*)d_in[6];
    const float* W2 = (const float*)d_in[7];
    const float* g2 = (const float*)d_in[8];
    const float* b2 = (const float*)d_in[9];
    const float* m2 = (const float*)d_in[10];
    const float* v2 = (const float*)d_in[11];
    float* out = (float*)d_out;

    int total_nb = (in_sizes[0] / 3) * 16;   // B*N*K = 2,097,152

    lse_fold_params<<<1, 32>>>(W1, g1, b1, m1, v1, W2, g2, b2, m2, v2);

    // Stage folded params into the constant bank (graph-capturable D2D memcpy).
    void* src = nullptr;
    cudaGetSymbolAddress(&src, g_params);
    cudaMemcpyToSymbolAsync(c_params, src, 60 * sizeof(float), 0,
                            cudaMemcpyDeviceToDevice, 0);

    int threads = 256;
    int per_block = threads * LSE_ITER;
    int blocks = (total_nb + per_block - 1) / per_block;
    lse_main<<<blocks, threads>>>(coords, nbr, out, total_nb);
}

// round 14
// speedup vs baseline: 5.3675x; 5.3675x over previous
#include <cuda_runtime.h>
#include <cuda_bf16.h>

#define LSE_EPS 1e-5f
#define LSE_ITER 4
#define WBUF_WORDS 288   // padded: neighbor n at word n*8 + (n>>2)*4, max 284

// Folded parameters: W1f[16] (o*4+c), t1[4] @16, W2f[32] @20 (o*4+c), t2[8] @52
__constant__ float c_params[60];

// Fold kernel writes the __constant__ backing store directly (device address
// passed from host via cudaGetSymbolAddress). The constant cache is flushed at
// launch boundaries, so lse_main reads fresh values — no memcpy node needed.
__global__ void lse_fold_params(float* __restrict__ cp,
                                const float* __restrict__ W1, const float* __restrict__ g1,
                                const float* __restrict__ b1, const float* __restrict__ m1,
                                const float* __restrict__ v1,
                                const float* __restrict__ W2, const float* __restrict__ g2,
                                const float* __restrict__ b2, const float* __restrict__ m2,
                                const float* __restrict__ v2) {
    int i = threadIdx.x;
    if (i < 4) {
        float s = g1[i] * rsqrtf(v1[i] + LSE_EPS);
        #pragma unroll
        for (int c = 0; c < 4; c++) cp[i * 4 + c] = W1[i * 4 + c] * s;
        cp[16 + i] = b1[i] - m1[i] * s;
    }
    if (i < 8) {
        float s = g2[i] * rsqrtf(v2[i] + LSE_EPS);
        #pragma unroll
        for (int c = 0; c < 4; c++) cp[20 + i * 4 + c] = W2[i * 4 + c] * s;
        cp[52 + i] = b2[i] - m2[i] * s;
    }
}

// Padded staging offset: neighbor n's 8 floats start at word n*8 + (n>>2)*4.
// Conflict-free per 8-lane phase for both STS.128 and LDS.128.
__device__ __forceinline__ int lse_off(int n) {
    return n * 8 + ((n >> 2) << 2);
}

__device__ __forceinline__ void lse_compute(float nx, float ny, float nz,
                                            float cx, float cy, float cz,
                                            float* __restrict__ r) {
    float rx = nx - cx;
    float ry = ny - cy;
    float rz = nz - cz;
    // Plain sqrtf: under the harness's fast-math flags this is a single
    // MUFU.SQRT. (__frsqrt_rn / inline-asm variants both regressed badly.)
    float d  = sqrtf(fmaf(rx, rx, fmaf(ry, ry, rz * rz)));

    float h[4];
    #pragma unroll
    for (int o = 0; o < 4; o++) {
        float acc = c_params[16 + o];
        acc = fmaf(rx, c_params[o * 4 + 0], acc);
        acc = fmaf(ry, c_params[o * 4 + 1], acc);
        acc = fmaf(rz, c_params[o * 4 + 2], acc);
        acc = fmaf(d,  c_params[o * 4 + 3], acc);
        h[o] = fmaxf(acc, 0.0f);
    }

    #pragma unroll
    for (int o = 0; o < 8; o++) {
        float acc = c_params[52 + o];
        acc = fmaf(h[0], c_params[20 + o * 4 + 0], acc);
        acc = fmaf(h[1], c_params[20 + o * 4 + 1], acc);
        acc = fmaf(h[2], c_params[20 + o * 4 + 2], acc);
        acc = fmaf(h[3], c_params[20 + o * 4 + 3], acc);
        r[o] = fmaxf(acc, 0.0f);
    }
}

// Thread-per-neighbor, 4 neighbors/thread strided by blockDim. Loads batched
// up front for MLP. Stores staged through a DOUBLE-BUFFERED warp-private smem
// buffer (one syncwarp per iteration): write buf(it&1), sync, read buf(it&1);
// the it+2 reuse is ordered by the intervening sync of it+1.
__global__ __launch_bounds__(256, 6) void lse_main(const float* __restrict__ coords,
                                                   const float* __restrict__ nbr,
                                                   float* __restrict__ out,
                                                   int total_nb) {
    __shared__ float sbuf[8 * 2 * WBUF_WORDS];

    int lane = threadIdx.x & 31;
    int warp = threadIdx.x >> 5;
    float* wbuf = sbuf + warp * (2 * WBUF_WORDS);

    int base = blockIdx.x * (256 * LSE_ITER) + threadIdx.x;

    if (base + 256 * (LSE_ITER - 1) < total_nb) {
        float nx[LSE_ITER], ny[LSE_ITER], nz[LSE_ITER];
        float cx[LSE_ITER], cy[LSE_ITER], cz[LSE_ITER];
        #pragma unroll
        for (int it = 0; it < LSE_ITER; it++) {
            int g = base + it * 256;
            const float* p = nbr + (size_t)g * 3;
            nx[it] = __ldg(p + 0);
            ny[it] = __ldg(p + 1);
            nz[it] = __ldg(p + 2);
            int bn = g >> 4;
            const float* q = coords + (size_t)bn * 3;
            cx[it] = __ldg(q + 0);
            cy[it] = __ldg(q + 1);
            cz[it] = __ldg(q + 2);
        }

        #pragma unroll
        for (int it = 0; it < LSE_ITER; it++) {
            float* buf = wbuf + (it & 1) * WBUF_WORDS;

            float r[8];
            lse_compute(nx[it], ny[it], nz[it], cx[it], cy[it], cz[it], r);

            // Stage 32B result into padded smem (conflict-free STS.128 x2)
            float4* s = reinterpret_cast<float4*>(buf + lse_off(lane));
            s[0] = make_float4(r[0], r[1], r[2], r[3]);
            s[1] = make_float4(r[4], r[5], r[6], r[7]);
            __syncwarp();

            // Dense readback: float4 slot f -> neighbor f>>1, half f&1
            int f0 = lane, f1 = lane + 32;
            float4 v0 = *reinterpret_cast<const float4*>(
                buf + lse_off(f0 >> 1) + (f0 & 1) * 4);
            float4 v1 = *reinterpret_cast<const float4*>(
                buf + lse_off(f1 >> 1) + (f1 & 1) * 4);

            // Lane-dense global store: warp writes 1KB fully contiguous
            int g0 = (base - lane) + it * 256;           // warp's first neighbor
            float4* ob = reinterpret_cast<float4*>(out + (size_t)g0 * 8);
            ob[lane]      = v0;
            ob[lane + 32] = v1;
        }
    } else {
        // Tail path (not taken for the benchmark shape): direct stores.
        for (int it = 0; it < LSE_ITER; it++) {
            int g = base + it * 256;
            if (g < total_nb) {
                const float* p = nbr + (size_t)g * 3;
                int bn = g >> 4;
                const float* q = coords + (size_t)bn * 3;
                float r[8];
                lse_compute(__ldg(p), __ldg(p + 1), __ldg(p + 2),
                            __ldg(q), __ldg(q + 1), __ldg(q + 2), r);
                float4* ob = reinterpret_cast<float4*>(out + (size_t)g * 8);
                ob[0] = make_float4(r[0], r[1], r[2], r[3]);
                ob[1] = make_float4(r[4], r[5], r[6], r[7]);
            }
        }
    }
}

extern "C" void kernel_launch(void* const* d_in, const int* in_sizes, int n_in,
                              void* d_out, int out_size) {
    const float* coords = (const float*)d_in[0];   // (B,N,3)
    const float* nbr    = (const float*)d_in[1];   // (B,N,K,3)
    const float* W1 = (const float*)d_in[2];
    const float* g1 = (const float*)d_in[3];
    const float* b1 = (const float*)d_in[4];
    const float* m1 = (const float*)d_in[5];
    const float* v1 = (const float*)d_in[6];
    const float* W2 = (const float*)d_in[7];
    const float* g2 = (const float*)d_in[8];
    const float* b2 = (const float*)d_in[9];
    const float* m2 = (const float*)d_in[10];
    const float* v2 = (const float*)d_in[11];
    float* out = (float*)d_out;

    int total_nb = (in_sizes[0] / 3) * 16;   // B*N*K = 2,097,152

    // Device address of the __constant__ backing store (no allocation).
    static float* cp_dev = nullptr;
    if (!cp_dev) {
        void* p = nullptr;
        cudaGetSymbolAddress(&p, c_params);
        cp_dev = (float*)p;
    }

    lse_fold_params<<<1, 32>>>(cp_dev, W1, g1, b1, m1, v1, W2, g2, b2, m2, v2);

    int threads = 256;
    int per_block = threads * LSE_ITER;
    int blocks = (total_nb + per_block - 1) / per_block;
    lse_main<<<blocks, threads>>>(coords, nbr, out, total_nb);
}

// round 15
// speedup vs baseline: 5.4325x; 1.0121x over previous
#include <cuda_runtime.h>
#include <cuda_bf16.h>

#define LSE_EPS 1e-5f
#define LSE_ITER 4
#define WBUF_WORDS 288   // padded: neighbor n at word n*8 + (n>>2)*4, max 284

// Folded parameters: W1f[16] (o*4+c), t1[4] @16, W2f[32] @20 (o*4+c), t2[8] @52
__constant__ float c_params[60];

// Fold kernel writes the __constant__ backing store directly (device address
// passed from host). Triggers programmatic launch of lse_main immediately so
// the dependent grid's launch latency overlaps the fold.
__global__ void lse_fold_params(float* __restrict__ cp,
                                const float* __restrict__ W1, const float* __restrict__ g1,
                                const float* __restrict__ b1, const float* __restrict__ m1,
                                const float* __restrict__ v1,
                                const float* __restrict__ W2, const float* __restrict__ g2,
                                const float* __restrict__ b2, const float* __restrict__ m2,
                                const float* __restrict__ v2) {
    cudaTriggerProgrammaticLaunchCompletion();
    int i = threadIdx.x;
    if (i < 4) {
        float s = g1[i] * rsqrtf(v1[i] + LSE_EPS);
        #pragma unroll
        for (int c = 0; c < 4; c++) cp[i * 4 + c] = W1[i * 4 + c] * s;
        cp[16 + i] = b1[i] - m1[i] * s;
    }
    if (i < 8) {
        float s = g2[i] * rsqrtf(v2[i] + LSE_EPS);
        #pragma unroll
        for (int c = 0; c < 4; c++) cp[20 + i * 4 + c] = W2[i * 4 + c] * s;
        cp[52 + i] = b2[i] - m2[i] * s;
    }
}

// Padded staging offset: neighbor n's 8 floats start at word n*8 + (n>>2)*4.
// Conflict-free per 8-lane phase for both STS.128 and LDS.128.
__device__ __forceinline__ int lse_off(int n) {
    return n * 8 + ((n >> 2) << 2);
}

__device__ __forceinline__ void lse_compute(float nx, float ny, float nz,
                                            float cx, float cy, float cz,
                                            float* __restrict__ r) {
    float rx = nx - cx;
    float ry = ny - cy;
    float rz = nz - cz;
    // Plain sqrtf: single MUFU.SQRT under the harness's fast-math flags.
    float d  = sqrtf(fmaf(rx, rx, fmaf(ry, ry, rz * rz)));

    float h[4];
    #pragma unroll
    for (int o = 0; o < 4; o++) {
        float acc = c_params[16 + o];
        acc = fmaf(rx, c_params[o * 4 + 0], acc);
        acc = fmaf(ry, c_params[o * 4 + 1], acc);
        acc = fmaf(rz, c_params[o * 4 + 2], acc);
        acc = fmaf(d,  c_params[o * 4 + 3], acc);
        h[o] = fmaxf(acc, 0.0f);
    }

    #pragma unroll
    for (int o = 0; o < 8; o++) {
        float acc = c_params[52 + o];
        acc = fmaf(h[0], c_params[20 + o * 4 + 0], acc);
        acc = fmaf(h[1], c_params[20 + o * 4 + 1], acc);
        acc = fmaf(h[2], c_params[20 + o * 4 + 2], acc);
        acc = fmaf(h[3], c_params[20 + o * 4 + 3], acc);
        r[o] = fmaxf(acc, 0.0f);
    }
}

// Thread-per-neighbor, 4 neighbors/thread strided by blockDim. Loads batched
// up front (parameter-independent, so they run BEFORE the grid-dep sync and
// overlap the fold kernel). Stores staged through the double-buffered
// warp-private smem buffer; global writes are lane-dense float4.
__global__ __launch_bounds__(256, 6) void lse_main(const float* __restrict__ coords,
                                                   const float* __restrict__ nbr,
                                                   float* __restrict__ out,
                                                   int total_nb) {
    __shared__ float sbuf[8 * 2 * WBUF_WORDS];

    int lane = threadIdx.x & 31;
    int warp = threadIdx.x >> 5;
    float* wbuf = sbuf + warp * (2 * WBUF_WORDS);

    int base = blockIdx.x * (256 * LSE_ITER) + threadIdx.x;

    if (base + 256 * (LSE_ITER - 1) < total_nb) {
        float nx[LSE_ITER], ny[LSE_ITER], nz[LSE_ITER];
        float cx[LSE_ITER], cy[LSE_ITER], cz[LSE_ITER];
        #pragma unroll
        for (int it = 0; it < LSE_ITER; it++) {
            int g = base + it * 256;
            const float* p = nbr + (size_t)g * 3;
            nx[it] = __ldg(p + 0);
            ny[it] = __ldg(p + 1);
            nz[it] = __ldg(p + 2);
            int bn = g >> 4;
            const float* q = coords + (size_t)bn * 3;
            cx[it] = __ldg(q + 0);
            cy[it] = __ldg(q + 1);
            cz[it] = __ldg(q + 2);
        }

        // Wait for the fold kernel (PDL edge) before touching c_params.
        cudaGridDependencySynchronize();

        #pragma unroll
        for (int it = 0; it < LSE_ITER; it++) {
            float* buf = wbuf + (it & 1) * WBUF_WORDS;

            float r[8];
            lse_compute(nx[it], ny[it], nz[it], cx[it], cy[it], cz[it], r);

            // Stage 32B result into padded smem (conflict-free STS.128 x2)
            float4* s = reinterpret_cast<float4*>(buf + lse_off(lane));
            s[0] = make_float4(r[0], r[1], r[2], r[3]);
            s[1] = make_float4(r[4], r[5], r[6], r[7]);
            __syncwarp();

            // Dense readback: float4 slot f -> neighbor f>>1, half f&1
            int f0 = lane, f1 = lane + 32;
            float4 v0 = *reinterpret_cast<const float4*>(
                buf + lse_off(f0 >> 1) + (f0 & 1) * 4);
            float4 v1 = *reinterpret_cast<const float4*>(
                buf + lse_off(f1 >> 1) + (f1 & 1) * 4);

            // Lane-dense global store: warp writes 1KB fully contiguous
            int g0 = (base - lane) + it * 256;           // warp's first neighbor
            float4* ob = reinterpret_cast<float4*>(out + (size_t)g0 * 8);
            ob[lane]      = v0;
            ob[lane + 32] = v1;
        }
    } else {
        // Tail path (not taken for the benchmark shape): direct stores.
        cudaGridDependencySynchronize();
        for (int it = 0; it < LSE_ITER; it++) {
            int g = base + it * 256;
            if (g < total_nb) {
                const float* p = nbr + (size_t)g * 3;
                int bn = g >> 4;
                const float* q = coords + (size_t)bn * 3;
                float r[8];
                lse_compute(__ldg(p), __ldg(p + 1), __ldg(p + 2),
                            __ldg(q), __ldg(q + 1), __ldg(q + 2), r);
                float4* ob = reinterpret_cast<float4*>(out + (size_t)g * 8);
                ob[0] = make_float4(r[0], r[1], r[2], r[3]);
                ob[1] = make_float4(r[4], r[5], r[6], r[7]);
            }
        }
    }
}

extern "C" void kernel_launch(void* const* d_in, const int* in_sizes, int n_in,
                              void* d_out, int out_size) {
    const float* coords = (const float*)d_in[0];   // (B,N,3)
    const float* nbr    = (const float*)d_in[1];   // (B,N,K,3)
    const float* W1 = (const float*)d_in[2];
    const float* g1 = (const float*)d_in[3];
    const float* b1 = (const float*)d_in[4];
    const float* m1 = (const float*)d_in[5];
    const float* v1 = (const float*)d_in[6];
    const float* W2 = (const float*)d_in[7];
    const float* g2 = (const float*)d_in[8];
    const float* b2 = (const float*)d_in[9];
    const float* m2 = (const float*)d_in[10];
    const float* v2 = (const float*)d_in[11];
    float* out = (float*)d_out;

    int total_nb = (in_sizes[0] / 3) * 16;   // B*N*K = 2,097,152

    // Device address of the __constant__ backing store (no allocation).
    static float* cp_dev = nullptr;
    if (!cp_dev) {
        void* p = nullptr;
        cudaGetSymbolAddress(&p, c_params);
        cp_dev = (float*)p;
    }

    lse_fold_params<<<1, 32>>>(cp_dev, W1, g1, b1, m1, v1, W2, g2, b2, m2, v2);

    // Launch lse_main as a programmatic dependent of the fold kernel: its
    // launch latency and load prologue overlap the fold's execution; the
    // grid-dep sync inside orders the c_params reads.
    int threads = 256;
    int per_block = threads * LSE_ITER;
    int blocks = (total_nb + per_block - 1) / per_block;

    cudaLaunchConfig_t cfg = {};
    cfg.gridDim  = dim3((unsigned)blocks, 1, 1);
    cfg.blockDim = dim3((unsigned)threads, 1, 1);
    cfg.dynamicSmemBytes = 0;
    cfg.stream = 0;
    cudaLaunchAttribute attrs[1];
    attrs[0].id = cudaLaunchAttributeProgrammaticStreamSerialization;
    attrs[0].val.programmaticStreamSerializationAllowed = 1;
    cfg.attrs = attrs;
    cfg.numAttrs = 1;

    cudaLaunchKernelEx(&cfg, lse_main, coords, nbr, out, total_nb);
}